// round 2
// baseline (speedup 1.0000x reference)
#include <cuda_runtime.h>
#include <cstdint>

// Problem constants (fixed shapes from the reference)
#define BB 16
#define CC 64
#define HH 192
#define WWID 192
#define HWSZ (HH * WWID)          // 36864
#define NSTEPS (BB * 128 * 512)   // 1,048,576 path steps total

// Scratch: per-pixel "was this pixel touched by any path" flag.
__device__ unsigned char g_occ[BB * HWSZ];   // 589,824 bytes
__device__ int g_idx_is64;                   // dtype flag for path_idx

// ---------------------------------------------------------------------------
// Kernel 1: zero the occupancy flags + reset dtype flag
// ---------------------------------------------------------------------------
__global__ void zero_occ_kernel() {
    int i = blockIdx.x * blockDim.x + threadIdx.x;
    uint4* p = reinterpret_cast<uint4*>(g_occ);
    if (i < (BB * HWSZ) / 16) p[i] = make_uint4(0u, 0u, 0u, 0u);
    if (i == 0) g_idx_is64 = 1;
}

// ---------------------------------------------------------------------------
// Kernel 1b: probe path_idx element width. View buffer as int32 words and
// test the odd words of the first 1024 pairs. int64 data (values < 36864)
// has hi-words == 0 always; int32 random data in [0,36864) makes 1024
// consecutive zeros essentially impossible.
// ---------------------------------------------------------------------------
__global__ void probe_dtype_kernel(const int* __restrict__ words) {
    int i = blockIdx.x * blockDim.x + threadIdx.x;   // 1024 threads
    if (words[2 * i + 1] != 0) atomicAnd(&g_idx_is64, 0);
}

// ---------------------------------------------------------------------------
// Kernel 2: mark occupancy from path_idx. Idempotent byte stores, no atomics.
// ---------------------------------------------------------------------------
__global__ void mark_occ_kernel(const void* __restrict__ path_idx) {
    int i = blockIdx.x * blockDim.x + threadIdx.x;
    if (i < NSTEPS) {
        int b = i >> 16;                 // P*L = 65536 steps per batch
        int hw;
        if (g_idx_is64)
            hw = (int)((const long long*)path_idx)[i];
        else
            hw = ((const int*)path_idx)[i];
        // clamp defensively (garbage index would corrupt, not crash elsewhere)
        if ((unsigned)hw < (unsigned)HWSZ)
            g_occ[b * HWSZ + hw] = 1;
    }
}

// ---------------------------------------------------------------------------
// Kernel 3: masked GEMM.
//   out[b][c][hw] = occ[b][hw] ? sum_k feat[b][k][hw] * W[k][c] + bias[c] : 0
// Per block: 128 pixels x all 64 channels, K=64 fully staged in shared.
// Each thread: 8 channels x 4 pixels = 32 outputs, computed as 4 channel-PAIRS
// via packed fma.rn.f32x2 (FFMA2). Channel pairs are adjacent in sW rows, so
// the packed W operands fall directly out of LDS.128 register quads.
// ---------------------------------------------------------------------------
__global__ void __launch_bounds__(256)
gemm_mask_kernel(const float* __restrict__ feat,
                 const float* __restrict__ Wm,     // [64][64] row-major (k, c)
                 const float* __restrict__ bm,     // [64]
                 float* __restrict__ out) {
    __shared__ float sW[64 * 64];    // 16 KB
    __shared__ float sF[64 * 128];   // 32 KB

    const int b   = blockIdx.y;
    const int hw0 = blockIdx.x * 128;
    const int tid = threadIdx.x;

    // Stage W (4096 floats) as float4
    {
        const float4* gw = reinterpret_cast<const float4*>(Wm);
        float4* sw = reinterpret_cast<float4*>(sW);
        #pragma unroll
        for (int i = tid; i < 1024; i += 256) sw[i] = gw[i];
    }
    // Stage F tile: 64 rows (k) x 128 pixels, each row contiguous in gmem
    {
        const float* gf = feat + (size_t)b * CC * HWSZ + hw0;
        float4* sf = reinterpret_cast<float4*>(sF);
        #pragma unroll
        for (int i = tid; i < 2048; i += 256) {
            int k = i >> 5;        // row
            int x = i & 31;        // float4 within row
            sf[i] = reinterpret_cast<const float4*>(gf + (size_t)k * HWSZ)[x];
        }
    }
    __syncthreads();

    const int cg = tid & 7;        // channel group -> channels [cg*8, cg*8+8)
    const int pg = tid >> 3;       // pixel group   -> pixels   [pg*4, pg*4+4)
    const int c0 = cg * 8;
    const int p0 = pg * 4;

    // acc[j][p]: packed pair (channel c0+2j, c0+2j+1) for pixel p0+p
    unsigned long long acc[4][4];
    #pragma unroll
    for (int j = 0; j < 4; j++)
        #pragma unroll
        for (int p = 0; p < 4; p++) acc[j][p] = 0ull;

    #pragma unroll 8
    for (int k = 0; k < 64; k++) {
        // W channel pairs: two LDS.128 -> four even-aligned 64-bit regs
        ulonglong2 w01 = *reinterpret_cast<const ulonglong2*>(&sW[k * 64 + c0]);
        ulonglong2 w23 = *reinterpret_cast<const ulonglong2*>(&sW[k * 64 + c0 + 4]);
        unsigned long long wp0 = w01.x, wp1 = w01.y, wp2 = w23.x, wp3 = w23.y;

        // 4 pixel features, duplicated into (f,f) packed pairs
        float4 f = *reinterpret_cast<const float4*>(&sF[k * 128 + p0]);
        unsigned long long fd0, fd1, fd2, fd3;
        asm("mov.b64 %0, {%1, %1};" : "=l"(fd0) : "r"(__float_as_uint(f.x)));
        asm("mov.b64 %0, {%1, %1};" : "=l"(fd1) : "r"(__float_as_uint(f.y)));
        asm("mov.b64 %0, {%1, %1};" : "=l"(fd2) : "r"(__float_as_uint(f.z)));
        asm("mov.b64 %0, {%1, %1};" : "=l"(fd3) : "r"(__float_as_uint(f.w)));

        #pragma unroll
        for (int p = 0; p < 4; p++) {
            unsigned long long fd = (p == 0) ? fd0 : (p == 1) ? fd1 : (p == 2) ? fd2 : fd3;
            asm("fma.rn.f32x2 %0, %1, %2, %0;" : "+l"(acc[0][p]) : "l"(wp0), "l"(fd));
            asm("fma.rn.f32x2 %0, %1, %2, %0;" : "+l"(acc[1][p]) : "l"(wp1), "l"(fd));
            asm("fma.rn.f32x2 %0, %1, %2, %0;" : "+l"(acc[2][p]) : "l"(wp2), "l"(fd));
            asm("fma.rn.f32x2 %0, %1, %2, %0;" : "+l"(acc[3][p]) : "l"(wp3), "l"(fd));
        }
    }

    // Epilogue: mask by occupancy, add bias, store 8 channel rows x 4 pixels
    uchar4 oc = *reinterpret_cast<const uchar4*>(g_occ + b * HWSZ + hw0 + p0);
    float msk[4];
    msk[0] = oc.x ? 1.0f : 0.0f;
    msk[1] = oc.y ? 1.0f : 0.0f;
    msk[2] = oc.z ? 1.0f : 0.0f;
    msk[3] = oc.w ? 1.0f : 0.0f;

    float bias[8];
    #pragma unroll
    for (int i = 0; i < 8; i++) bias[i] = __ldg(&bm[c0 + i]);

    float* obase = out + ((size_t)b * CC + c0) * HWSZ + hw0 + p0;
    #pragma unroll
    for (int j = 0; j < 4; j++) {
        float lo[4], hi[4];
        #pragma unroll
        for (int p = 0; p < 4; p++) {
            unsigned int l, h;
            asm("mov.b64 {%0, %1}, %2;" : "=r"(l), "=r"(h) : "l"(acc[j][p]));
            lo[p] = __uint_as_float(l);
            hi[p] = __uint_as_float(h);
        }
        float bA = bias[2 * j], bB = bias[2 * j + 1];
        float4 rA = make_float4((lo[0] + bA) * msk[0], (lo[1] + bA) * msk[1],
                                (lo[2] + bA) * msk[2], (lo[3] + bA) * msk[3]);
        float4 rB = make_float4((hi[0] + bB) * msk[0], (hi[1] + bB) * msk[1],
                                (hi[2] + bB) * msk[2], (hi[3] + bB) * msk[3]);
        *reinterpret_cast<float4*>(obase + (size_t)(2 * j) * HWSZ)     = rA;
        *reinterpret_cast<float4*>(obase + (size_t)(2 * j + 1) * HWSZ) = rB;
    }
}

// ---------------------------------------------------------------------------
extern "C" void kernel_launch(void* const* d_in, const int* in_sizes, int n_in,
                              void* d_out, int out_size) {
    const float* feat = (const float*)d_in[0];      // [B, C, H, W] f32
    const void*  pidx = d_in[1];                    // [B, P, L] int32 OR int64
    const float* Wm   = (const float*)d_in[2];      // [C, C] f32
    const float* bm   = (const float*)d_in[3];      // [C] f32
    float*       out  = (float*)d_out;              // [B, C, H, W] f32

    (void)in_sizes; (void)n_in; (void)out_size;

    zero_occ_kernel<<<(BB * HWSZ / 16 + 255) / 256, 256>>>();
    probe_dtype_kernel<<<4, 256>>>((const int*)pidx);
    mark_occ_kernel<<<(NSTEPS + 255) / 256, 256>>>(pidx);

    dim3 grid(HWSZ / 128, BB);   // 288 x 16 blocks
    gemm_mask_kernel<<<grid, 256>>>(feat, Wm, bm, out);
}

// round 3
// speedup vs baseline: 1.4985x; 1.4985x over previous
#include <cuda_runtime.h>
#include <cstdint>

#define BB 16
#define CC 64
#define HH 192
#define WWID 192
#define HWSZ (HH * WWID)          // 36864
#define NSTEPS (BB * 128 * 512)   // 1,048,576 path steps total
#define PXT 256                   // pixels per block

__device__ unsigned char g_occ[BB * HWSZ];
__device__ int g_idx_is64;

// ---------------------------------------------------------------------------
__global__ void zero_occ_kernel() {
    int i = blockIdx.x * blockDim.x + threadIdx.x;
    uint4* p = reinterpret_cast<uint4*>(g_occ);
    if (i < (BB * HWSZ) / 16) p[i] = make_uint4(0u, 0u, 0u, 0u);
    if (i == 0) g_idx_is64 = 1;
}

// Probe path_idx width: odd int32 words all zero over 1024 pairs => int64.
__global__ void probe_dtype_kernel(const int* __restrict__ words) {
    int i = blockIdx.x * blockDim.x + threadIdx.x;
    if (words[2 * i + 1] != 0) atomicAnd(&g_idx_is64, 0);
}

__global__ void mark_occ_kernel(const void* __restrict__ path_idx) {
    int i = blockIdx.x * blockDim.x + threadIdx.x;
    if (i < NSTEPS) {
        int b = i >> 16;
        int hw;
        if (g_idx_is64)
            hw = (int)((const long long*)path_idx)[i];
        else
            hw = ((const int*)path_idx)[i];
        if ((unsigned)hw < (unsigned)HWSZ)
            g_occ[b * HWSZ + hw] = 1;
    }
}

// ---------------------------------------------------------------------------
// Masked GEMM: out[b][c][hw] = occ ? sum_k feat[b][k][hw]*W[k][c] + bias[c] : 0
// Block: 256 pixels x 64 channels, 256 threads; thread tile 8ch x 8px.
// W stored as two half-row arrays so each warp's 8 channel-quads hit banks
// 0..31 exactly once (conflict-free). All work via packed fma.rn.f32x2.
// ---------------------------------------------------------------------------
__global__ void __launch_bounds__(256, 2)
gemm_mask_kernel(const float* __restrict__ feat,
                 const float* __restrict__ Wm,     // [64][64] (k, c)
                 const float* __restrict__ bm,     // [64]
                 float* __restrict__ out) {
    __shared__ float4 sW0[64 * 8];   // sW0[k*8+cg] = W[k][cg*8 .. cg*8+3]
    __shared__ float4 sW1[64 * 8];   // sW1[k*8+cg] = W[k][cg*8+4 .. cg*8+7]
    __shared__ float  sF[64 * PXT];  // 64 KB

    const int b   = blockIdx.y;
    const int hw0 = blockIdx.x * PXT;
    const int tid = threadIdx.x;

    // Stage W with the split layout (1024 float4s)
    {
        const float4* gw = reinterpret_cast<const float4*>(Wm);
        #pragma unroll
        for (int i = tid; i < 1024; i += 256) {
            int k = i >> 4;        // row
            int q = i & 15;        // quad within row (16 quads of 4 floats)
            float4 v = gw[i];
            if (q & 1) sW1[k * 8 + (q >> 1)] = v;
            else       sW0[k * 8 + (q >> 1)] = v;
        }
    }
    // Stage F tile: 64 rows x 256 pixels
    {
        const float* gf = feat + (size_t)b * CC * HWSZ + hw0;
        float4* sf = reinterpret_cast<float4*>(sF);
        #pragma unroll
        for (int i = tid; i < 64 * (PXT / 4); i += 256) {
            int k = i >> 6;        // row (64 float4 per row)
            int x = i & 63;
            sf[i] = reinterpret_cast<const float4*>(gf + (size_t)k * HWSZ)[x];
        }
    }
    __syncthreads();

    const int cg = tid & 7;        // channels [cg*8, cg*8+8)
    const int pg = tid >> 3;       // pixels   [pg*8, pg*8+8)
    const int c0 = cg * 8;
    const int p0 = pg * 8;

    // acc[j][p]: packed (channel c0+2j, c0+2j+1) for pixel p0+p
    unsigned long long acc[4][8];
    #pragma unroll
    for (int j = 0; j < 4; j++)
        #pragma unroll
        for (int p = 0; p < 8; p++) acc[j][p] = 0ull;

    #pragma unroll 8
    for (int k = 0; k < 64; k++) {
        // W: two conflict-free LDS.128 -> 4 packed channel pairs
        float4 wa = sW0[k * 8 + cg];
        float4 wb = sW1[k * 8 + cg];
        unsigned long long wp0, wp1, wp2, wp3;
        asm("mov.b64 %0, {%1, %2};" : "=l"(wp0) : "r"(__float_as_uint(wa.x)), "r"(__float_as_uint(wa.y)));
        asm("mov.b64 %0, {%1, %2};" : "=l"(wp1) : "r"(__float_as_uint(wa.z)), "r"(__float_as_uint(wa.w)));
        asm("mov.b64 %0, {%1, %2};" : "=l"(wp2) : "r"(__float_as_uint(wb.x)), "r"(__float_as_uint(wb.y)));
        asm("mov.b64 %0, {%1, %2};" : "=l"(wp3) : "r"(__float_as_uint(wb.z)), "r"(__float_as_uint(wb.w)));

        // F: 8 pixels via two LDS.128, duplicated into (f,f) pairs
        float4 fa = *reinterpret_cast<const float4*>(&sF[k * PXT + p0]);
        float4 fb = *reinterpret_cast<const float4*>(&sF[k * PXT + p0 + 4]);
        unsigned long long fd[8];
        asm("mov.b64 %0, {%1, %1};" : "=l"(fd[0]) : "r"(__float_as_uint(fa.x)));
        asm("mov.b64 %0, {%1, %1};" : "=l"(fd[1]) : "r"(__float_as_uint(fa.y)));
        asm("mov.b64 %0, {%1, %1};" : "=l"(fd[2]) : "r"(__float_as_uint(fa.z)));
        asm("mov.b64 %0, {%1, %1};" : "=l"(fd[3]) : "r"(__float_as_uint(fa.w)));
        asm("mov.b64 %0, {%1, %1};" : "=l"(fd[4]) : "r"(__float_as_uint(fb.x)));
        asm("mov.b64 %0, {%1, %1};" : "=l"(fd[5]) : "r"(__float_as_uint(fb.y)));
        asm("mov.b64 %0, {%1, %1};" : "=l"(fd[6]) : "r"(__float_as_uint(fb.z)));
        asm("mov.b64 %0, {%1, %1};" : "=l"(fd[7]) : "r"(__float_as_uint(fb.w)));

        #pragma unroll
        for (int p = 0; p < 8; p++) {
            asm("fma.rn.f32x2 %0, %1, %2, %0;" : "+l"(acc[0][p]) : "l"(wp0), "l"(fd[p]));
            asm("fma.rn.f32x2 %0, %1, %2, %0;" : "+l"(acc[1][p]) : "l"(wp1), "l"(fd[p]));
            asm("fma.rn.f32x2 %0, %1, %2, %0;" : "+l"(acc[2][p]) : "l"(wp2), "l"(fd[p]));
            asm("fma.rn.f32x2 %0, %1, %2, %0;" : "+l"(acc[3][p]) : "l"(wp3), "l"(fd[p]));
        }
    }

    // Epilogue: occupancy mask, bias, store 8 channel rows x 8 pixels
    float msk[8];
    {
        const unsigned char* ob = g_occ + b * HWSZ + hw0 + p0;
        uint2 ow = *reinterpret_cast<const uint2*>(ob);
        #pragma unroll
        for (int p = 0; p < 4; p++) msk[p]     = ((ow.x >> (8 * p)) & 0xFF) ? 1.0f : 0.0f;
        #pragma unroll
        for (int p = 0; p < 4; p++) msk[4 + p] = ((ow.y >> (8 * p)) & 0xFF) ? 1.0f : 0.0f;
    }

    float bias[8];
    #pragma unroll
    for (int i = 0; i < 8; i++) bias[i] = __ldg(&bm[c0 + i]);

    float* obase = out + ((size_t)b * CC + c0) * HWSZ + hw0 + p0;
    #pragma unroll
    for (int j = 0; j < 4; j++) {
        float lo[8], hi[8];
        #pragma unroll
        for (int p = 0; p < 8; p++) {
            unsigned int l, h;
            asm("mov.b64 {%0, %1}, %2;" : "=r"(l), "=r"(h) : "l"(acc[j][p]));
            lo[p] = __uint_as_float(l);
            hi[p] = __uint_as_float(h);
        }
        float bA = bias[2 * j], bB = bias[2 * j + 1];
        float* rowA = obase + (size_t)(2 * j) * HWSZ;
        float* rowB = obase + (size_t)(2 * j + 1) * HWSZ;
        *reinterpret_cast<float4*>(rowA) =
            make_float4((lo[0] + bA) * msk[0], (lo[1] + bA) * msk[1],
                        (lo[2] + bA) * msk[2], (lo[3] + bA) * msk[3]);
        *reinterpret_cast<float4*>(rowA + 4) =
            make_float4((lo[4] + bA) * msk[4], (lo[5] + bA) * msk[5],
                        (lo[6] + bA) * msk[6], (lo[7] + bA) * msk[7]);
        *reinterpret_cast<float4*>(rowB) =
            make_float4((hi[0] + bB) * msk[0], (hi[1] + bB) * msk[1],
                        (hi[2] + bB) * msk[2], (hi[3] + bB) * msk[3]);
        *reinterpret_cast<float4*>(rowB + 4) =
            make_float4((hi[4] + bB) * msk[4], (hi[5] + bB) * msk[5],
                        (hi[6] + bB) * msk[6], (hi[7] + bB) * msk[7]);
    }
}

// ---------------------------------------------------------------------------
extern "C" void kernel_launch(void* const* d_in, const int* in_sizes, int n_in,
                              void* d_out, int out_size) {
    const float* feat = (const float*)d_in[0];      // [B, C, H, W] f32
    const void*  pidx = d_in[1];                    // [B, P, L] int32 or int64
    const float* Wm   = (const float*)d_in[2];      // [C, C] f32
    const float* bm   = (const float*)d_in[3];      // [C] f32
    float*       out  = (float*)d_out;              // [B, C, H, W] f32

    (void)in_sizes; (void)n_in; (void)out_size;

    zero_occ_kernel<<<(BB * HWSZ / 16 + 255) / 256, 256>>>();
    probe_dtype_kernel<<<4, 256>>>((const int*)pidx);
    mark_occ_kernel<<<(NSTEPS + 255) / 256, 256>>>(pidx);

    dim3 grid(HWSZ / PXT, BB);   // 144 x 16 blocks
    gemm_mask_kernel<<<grid, 256>>>(feat, Wm, bm, out);
}

// round 6
// speedup vs baseline: 1.8620x; 1.2425x over previous
#include <cuda_runtime.h>
#include <cuda_bf16.h>
#include <cstdint>

#define BB 16
#define CC 64
#define HH 192
#define WWID 192
#define HWSZ (HH * WWID)          // 36864
#define NSTEPS (BB * 128 * 512)   // 1,048,576 path steps
#define TPX 128                   // pixels per block tile (MMA M)

__device__ unsigned char g_occ[BB * HWSZ];
__device__ int g_idx_is64;

// ---------------------------------------------------------------------------
__global__ void zero_occ_kernel() {
    int i = blockIdx.x * blockDim.x + threadIdx.x;
    uint4* p = reinterpret_cast<uint4*>(g_occ);
    if (i < (BB * HWSZ) / 16) p[i] = make_uint4(0u, 0u, 0u, 0u);
    if (i == 0) g_idx_is64 = 1;
}

__global__ void probe_dtype_kernel(const int* __restrict__ words) {
    int i = blockIdx.x * blockDim.x + threadIdx.x;   // 1024 threads
    if (words[2 * i + 1] != 0) atomicAnd(&g_idx_is64, 0);
}

__global__ void mark_occ_kernel(const void* __restrict__ path_idx) {
    int i = blockIdx.x * blockDim.x + threadIdx.x;
    if (i < NSTEPS) {
        int b = i >> 16;
        int hw;
        if (g_idx_is64)
            hw = (int)((const long long*)path_idx)[i];
        else
            hw = ((const int*)path_idx)[i];
        if ((unsigned)hw < (unsigned)HWSZ)
            g_occ[b * HWSZ + hw] = 1;
    }
}

// ---------------------------------------------------------------------------
__device__ __forceinline__ uint32_t smem_u32(const void* p) {
    uint32_t a;
    asm("{ .reg .u64 t; cvta.to.shared.u64 t, %1; cvt.u32.u64 %0, t; }"
        : "=r"(a) : "l"(p));
    return a;
}
// SW128-style swizzle on 128B rows of 16B chunks
#define SWZ(o) ((uint32_t)(o) ^ ((((uint32_t)(o)) >> 3) & 0x70))

#define LDSM4(R, ADDR)                                                        \
    asm volatile("ldmatrix.sync.aligned.m8n8.x4.shared.b16 {%0,%1,%2,%3}, [%4];" \
                 : "=r"((R)[0]), "=r"((R)[1]), "=r"((R)[2]), "=r"((R)[3])     \
                 : "r"(ADDR))

#define MMA16816(C, A, B0, B1)                                                \
    asm volatile("mma.sync.aligned.m16n8k16.row.col.f32.bf16.bf16.f32 "       \
                 "{%0,%1,%2,%3}, {%4,%5,%6,%7}, {%8,%9}, {%0,%1,%2,%3};"      \
                 : "+f"((C)[0]), "+f"((C)[1]), "+f"((C)[2]), "+f"((C)[3])     \
                 : "r"((A)[0]), "r"((A)[1]), "r"((A)[2]), "r"((A)[3]),        \
                   "r"(B0), "r"(B1))

// ---------------------------------------------------------------------------
// Masked GEMM via mma.sync bf16 3-way split (hi*hi + hi*lo + lo*hi, f32 acc).
// D[128 px][64 ch] = A[px][k] * Bt[ch][k]^T ; A = transposed feat tile,
// Bt = W^T. SW128-swizzled SMEM rows of 128B -> conflict-free ldmatrix.
// Swizzle XOR is applied to the fully-composed chunk offset (no carry).
// ---------------------------------------------------------------------------
__global__ void __launch_bounds__(128)
mma_gemm_kernel(const float* __restrict__ feat,
                const float* __restrict__ Wm,     // [64][64] (k, c)
                const float* __restrict__ bm,     // [64]
                float* __restrict__ out) {
    __shared__ __align__(1024) unsigned char sAhi[TPX * 128];  // 16 KB
    __shared__ __align__(1024) unsigned char sAlo[TPX * 128];  // 16 KB
    __shared__ __align__(1024) unsigned char sBhi[64 * 128];   // 8 KB
    __shared__ __align__(1024) unsigned char sBlo[64 * 128];   // 8 KB (48 KB)

    const int tid  = threadIdx.x;
    const int warp = tid >> 5;
    const int lane = tid & 31;
    const int b    = blockIdx.y;
    const int hw0  = blockIdx.x * TPX;

    // --- Stage B = W^T split. Bt[n][k] = Wm[k][n]; rows of 64 bf16 = 128 B ---
    for (int i = tid; i < 64 * 64; i += 128) {
        int n = i & 63;           // lanes -> consecutive n (coalesced gmem read)
        int k = i >> 6;
        float w = Wm[k * 64 + n];
        __nv_bfloat16 h = __float2bfloat16(w);
        __nv_bfloat16 l = __float2bfloat16(w - __bfloat162float(h));
        uint32_t off = SWZ((uint32_t)(n * 128 + k * 2));
        *reinterpret_cast<unsigned short*>(sBhi + off) = __bfloat16_as_ushort(h);
        *reinterpret_cast<unsigned short*>(sBlo + off) = __bfloat16_as_ushort(l);
    }

    // --- Stage A: thread = pixel; read F[k][px] coalesced, write A[px][k] ---
    {
        const float* fbase = feat + (size_t)b * CC * HWSZ + hw0 + tid;
        const uint32_t arow = (uint32_t)tid * 128;
        #pragma unroll
        for (int c = 0; c < 8; c++) {          // 8 chunks x 8 k-values (16 B)
            uint32_t hp[4], lp[4];
            #pragma unroll
            for (int j = 0; j < 4; j++) {
                int k0 = c * 8 + 2 * j;
                float a0 = fbase[(size_t)k0 * HWSZ];
                float a1 = fbase[(size_t)(k0 + 1) * HWSZ];
                __nv_bfloat16 h0 = __float2bfloat16(a0);
                __nv_bfloat16 h1 = __float2bfloat16(a1);
                __nv_bfloat16 l0 = __float2bfloat16(a0 - __bfloat162float(h0));
                __nv_bfloat16 l1 = __float2bfloat16(a1 - __bfloat162float(h1));
                hp[j] = (uint32_t)__bfloat16_as_ushort(h0) |
                        ((uint32_t)__bfloat16_as_ushort(h1) << 16);
                lp[j] = (uint32_t)__bfloat16_as_ushort(l0) |
                        ((uint32_t)__bfloat16_as_ushort(l1) << 16);
            }
            uint32_t off = SWZ(arow + c * 16);
            asm volatile("st.shared.v4.b32 [%0], {%1, %2, %3, %4};"
                         :: "r"(smem_u32(sAhi) + off),
                            "r"(hp[0]), "r"(hp[1]), "r"(hp[2]), "r"(hp[3]) : "memory");
            asm volatile("st.shared.v4.b32 [%0], {%1, %2, %3, %4};"
                         :: "r"(smem_u32(sAlo) + off),
                            "r"(lp[0]), "r"(lp[1]), "r"(lp[2]), "r"(lp[3]) : "memory");
        }
    }
    __syncthreads();

    // --- Fragment addressing (XOR applied to composed chunk offset) ---
    const int g = lane >> 2, t = lane & 3;
    const int px = warp * 32;
    const uint32_t mask   = (uint32_t)(lane & 7) << 4;      // row&7 swizzle
    const uint32_t aRow   = (uint32_t)(px + (lane & 15)) * 128;
    const uint32_t aChunk = (uint32_t)(lane & 16);           // k-half select
    const uint32_t bRow   = (uint32_t)((lane & 7) + ((lane & 16) >> 1)) * 128;
    const uint32_t bChunk = (uint32_t)((lane & 8) << 1);     // k-half select

    float c_[2][8][4];
    #pragma unroll
    for (int m = 0; m < 2; m++)
        #pragma unroll
        for (int n = 0; n < 8; n++)
            #pragma unroll
            for (int r = 0; r < 4; r++) c_[m][n][r] = 0.0f;

    const uint32_t aBases[3] = { smem_u32(sAhi), smem_u32(sAhi), smem_u32(sAlo) };
    const uint32_t bBases[3] = { smem_u32(sBhi), smem_u32(sBlo), smem_u32(sBhi) };

    #pragma unroll
    for (int ps = 0; ps < 3; ps++) {
        const uint32_t aB = aBases[ps] + aRow;
        const uint32_t bB = bBases[ps] + bRow;
        #pragma unroll
        for (int k = 0; k < 4; k++) {
            const uint32_t ac = (aChunk + (uint32_t)k * 32) ^ mask;  // <=112, no carry
            const uint32_t bc = (bChunk + (uint32_t)k * 32) ^ mask;
            uint32_t a0[4], a1[4];
            LDSM4(a0, aB + ac);
            LDSM4(a1, aB + 2048 + ac);
            uint32_t bf[8][2];
            #pragma unroll
            for (int np = 0; np < 4; np++) {
                uint32_t r4[4];
                LDSM4(r4, bB + (uint32_t)np * 2048 + bc);
                bf[2 * np][0] = r4[0]; bf[2 * np][1] = r4[1];
                bf[2 * np + 1][0] = r4[2]; bf[2 * np + 1][1] = r4[3];
            }
            #pragma unroll
            for (int n = 0; n < 8; n++) {
                MMA16816(c_[0][n], a0, bf[n][0], bf[n][1]);
                MMA16816(c_[1][n], a1, bf[n][0], bf[n][1]);
            }
        }
    }

    // --- Epilogue: mask + bias; per-channel stores are full 32B sectors ---
    float bias0[8], bias1[8];
    #pragma unroll
    for (int n = 0; n < 8; n++) {
        bias0[n] = __ldg(&bm[n * 8 + 2 * t]);
        bias1[n] = __ldg(&bm[n * 8 + 2 * t + 1]);
    }
    const unsigned char* occ = g_occ + b * HWSZ + hw0 + px + g;
    float msk[4];
    msk[0] = occ[0]  ? 1.0f : 0.0f;   // m=0 row g
    msk[1] = occ[8]  ? 1.0f : 0.0f;   // m=0 row g+8
    msk[2] = occ[16] ? 1.0f : 0.0f;   // m=1 row g
    msk[3] = occ[24] ? 1.0f : 0.0f;   // m=1 row g+8

    float* ob = out + (size_t)b * CC * HWSZ;
    #pragma unroll
    for (int m = 0; m < 2; m++) {
        const int hwA = hw0 + px + m * 16 + g;
        const int hwB = hwA + 8;
        const float mA = msk[2 * m], mB = msk[2 * m + 1];
        #pragma unroll
        for (int n = 0; n < 8; n++) {
            const size_t ch = (size_t)(n * 8 + 2 * t);
            ob[ch * HWSZ + hwA]       = (c_[m][n][0] + bias0[n]) * mA;
            ob[(ch + 1) * HWSZ + hwA] = (c_[m][n][1] + bias1[n]) * mA;
            ob[ch * HWSZ + hwB]       = (c_[m][n][2] + bias0[n]) * mB;
            ob[(ch + 1) * HWSZ + hwB] = (c_[m][n][3] + bias1[n]) * mB;
        }
    }
}

// ---------------------------------------------------------------------------
extern "C" void kernel_launch(void* const* d_in, const int* in_sizes, int n_in,
                              void* d_out, int out_size) {
    const float* feat = (const float*)d_in[0];      // [B, C, H, W] f32
    const void*  pidx = d_in[1];                    // [B, P, L] int32 or int64
    const float* Wm   = (const float*)d_in[2];      // [C, C] f32
    const float* bm   = (const float*)d_in[3];      // [C] f32
    float*       out  = (float*)d_out;              // [B, C, H, W] f32

    (void)in_sizes; (void)n_in; (void)out_size;

    zero_occ_kernel<<<(BB * HWSZ / 16 + 255) / 256, 256>>>();
    probe_dtype_kernel<<<4, 256>>>((const int*)pidx);
    mark_occ_kernel<<<(NSTEPS + 255) / 256, 256>>>(pidx);

    dim3 grid(HWSZ / TPX, BB);   // 288 x 16 = 4608 tiles
    mma_gemm_kernel<<<grid, 128>>>(feat, Wm, bm, out);
}